// round 6
// baseline (speedup 1.0000x reference)
#include <cuda_runtime.h>
#include <cuda_bf16.h>
#include <math.h>
#include <stdint.h>

#define HID 128
#define MAX_N 100352
#define MAXSTEPS 8
#define NG 256
#define MAX_E 2000000

// ---------------- scratch (static device globals; no runtime allocation) ----
__device__ __align__(16) float    g_h   [MAX_N * HID];
__device__ __align__(16) float    g_out1[MAX_N * 512];
__device__ __align__(16) float    g_gi  [MAX_N * 384];
__device__ __align__(16) uint32_t g_hH  [MAX_N * 64];
__device__ __align__(16) uint32_t g_hL  [MAX_N * 64];
__device__ __align__(16) uint32_t g_aggH[MAX_N * 64];
__device__ __align__(16) uint32_t g_aggL[MAX_N * 64];
__device__ __align__(16) uint32_t g_xH  [MAX_N * 48];
__device__ __align__(16) uint32_t g_xL  [MAX_N * 48];
__device__ __align__(16) uint32_t g_WcatH[MAXSTEPS * 64 * 512];
__device__ __align__(16) uint32_t g_WcatL[MAXSTEPS * 64 * 512];
__device__ __align__(16) uint32_t g_WihTH[64 * 384];
__device__ __align__(16) uint32_t g_WihTL[64 * 384];
__device__ __align__(16) uint32_t g_WembH[48 * 128];
__device__ __align__(16) uint32_t g_WembL[48 * 128];
__device__ int g_deg[MAX_N];
__device__ int g_rowptr[MAX_N + 1];
__device__ int g_cursor[MAX_N];
__device__ int g_esrc[MAX_E];
__device__ int g_starts[NG + 1];

// ---------------- helpers ----------------------------------------------------
__device__ __forceinline__ void split2(float x, float y, uint32_t& hi, uint32_t& lo) {
    __nv_bfloat16 hx = __float2bfloat16_rn(x);
    __nv_bfloat16 hy = __float2bfloat16_rn(y);
    float rx = x - __bfloat162float(hx);
    float ry = y - __bfloat162float(hy);
    __nv_bfloat162 h; h.x = hx; h.y = hy;
    __nv_bfloat162 l; l.x = __float2bfloat16_rn(rx); l.y = __float2bfloat16_rn(ry);
    hi = *(uint32_t*)&h;
    lo = *(uint32_t*)&l;
}

__device__ __forceinline__ void mma_bf16(float* c, const uint32_t* a, const uint32_t* b) {
    asm volatile(
        "mma.sync.aligned.m16n8k16.row.col.f32.bf16.bf16.f32 "
        "{%0,%1,%2,%3}, {%4,%5,%6,%7}, {%8,%9}, {%0,%1,%2,%3};\n"
        : "+f"(c[0]), "+f"(c[1]), "+f"(c[2]), "+f"(c[3])
        : "r"(a[0]), "r"(a[1]), "r"(a[2]), "r"(a[3]),
          "r"(b[0]), "r"(b[1]));
}

__device__ __forceinline__ void cp16(uint32_t saddr, const void* gaddr, bool pred) {
    int sz = pred ? 16 : 0;
    asm volatile("cp.async.cg.shared.global [%0], [%1], 16, %2;\n"
                 :: "r"(saddr), "l"(gaddr), "r"(sz));
}
__device__ __forceinline__ void cp_commit() {
    asm volatile("cp.async.commit_group;\n");
}
__device__ __forceinline__ void cp_wait0() {
    asm volatile("cp.async.wait_group 0;\n");
}

__device__ __forceinline__ float sigmoidf_(float x) {
    return 1.0f / (1.0f + expf(-x));
}

// ---------------- small utility kernels --------------------------------------
__global__ void zero_i(int* p, int n) {
    int i = blockIdx.x * blockDim.x + threadIdx.x;
    if (i < n) p[i] = 0;
}

// ---------------- weight / input pre-split kernels ---------------------------
__global__ void pack_wcat_kernel(const float* __restrict__ Wm,
                                 const float* __restrict__ whh,
                                 uint32_t* __restrict__ WH, uint32_t* __restrict__ WL,
                                 int steps) {
    int idx = blockIdx.x * blockDim.x + threadIdx.x;
    int total = steps * 64 * 512;
    if (idx >= total) return;
    int s = idx / (64 * 512);
    int rem = idx % (64 * 512);
    int p = rem / 512;
    int j = rem % 512;
    float a, b;
    if (j < HID) {
        a = Wm[s * HID * HID + (2 * p) * HID + j];
        b = Wm[s * HID * HID + (2 * p + 1) * HID + j];
    } else {
        int jj = j - HID;
        a = whh[jj * HID + 2 * p];
        b = whh[jj * HID + 2 * p + 1];
    }
    uint32_t h, l;
    split2(a, b, h, l);
    WH[idx] = h; WL[idx] = l;
}

__global__ void pack_wihT_kernel(const float* __restrict__ wih,
                                 uint32_t* __restrict__ WH, uint32_t* __restrict__ WL) {
    int idx = blockIdx.x * blockDim.x + threadIdx.x;
    if (idx >= 64 * 384) return;
    int p = idx / 384;
    int j = idx % 384;
    uint32_t h, l;
    split2(wih[j * HID + 2 * p], wih[j * HID + 2 * p + 1], h, l);
    WH[idx] = h; WL[idx] = l;
}

__global__ void pack_wemb_kernel(const float* __restrict__ We,
                                 uint32_t* __restrict__ WH, uint32_t* __restrict__ WL,
                                 int KPx) {
    int idx = blockIdx.x * blockDim.x + threadIdx.x;
    if (idx >= 48 * 128) return;
    int p = idx / 128;
    int j = idx % 128;
    uint32_t h = 0, l = 0;
    if (p < KPx) split2(We[(2 * p) * HID + j], We[(2 * p + 1) * HID + j], h, l);
    WH[idx] = h; WL[idx] = l;
}

__global__ void split_x_kernel(const float* __restrict__ x,
                               uint32_t* __restrict__ xH, uint32_t* __restrict__ xL,
                               int Nn, int F, int KPx, int Apx) {
    long long idx = (long long)blockIdx.x * blockDim.x + threadIdx.x;
    if (idx >= (long long)Nn * Apx) return;
    int n = (int)(idx / Apx);
    int p = (int)(idx % Apx);
    uint32_t h = 0, l = 0;
    if (p < KPx) split2(x[(long long)n * F + 2 * p], x[(long long)n * F + 2 * p + 1], h, l);
    xH[idx] = h; xL[idx] = l;
}

// ---------------- CSR build ---------------------------------------------------
__global__ void hist_kernel(const int* __restrict__ ei, long long E, int* __restrict__ deg) {
    long long e = (long long)blockIdx.x * blockDim.x + threadIdx.x;
    if (e >= E) return;
    atomicAdd(&deg[ei[E + e]], 1);
}

__global__ void scan_kernel(const int* __restrict__ deg, int* __restrict__ rowptr,
                            int* __restrict__ cursor, int Nn) {
    __shared__ int warpsums[32];
    const int tid = threadIdx.x;
    const int lane = tid & 31;
    const int wid = tid >> 5;
    int carry = 0;
    for (int base = 0; base < Nn; base += 1024) {
        int idx = base + tid;
        int v = (idx < Nn) ? deg[idx] : 0;
        int x = v;
#pragma unroll
        for (int off = 1; off < 32; off <<= 1) {
            int y = __shfl_up_sync(0xffffffffu, x, off);
            if (lane >= off) x += y;
        }
        if (lane == 31) warpsums[wid] = x;
        __syncthreads();
        if (wid == 0) {
            int z = warpsums[lane];
#pragma unroll
            for (int off = 1; off < 32; off <<= 1) {
                int y = __shfl_up_sync(0xffffffffu, z, off);
                if (lane >= off) z += y;
            }
            warpsums[lane] = z;
        }
        __syncthreads();
        int pref = (wid > 0) ? warpsums[wid - 1] : 0;
        int excl = carry + pref + x - v;
        if (idx < Nn) { rowptr[idx] = excl; cursor[idx] = excl; }
        carry += warpsums[31];
        __syncthreads();
    }
    if (tid == 0) rowptr[Nn] = carry;
}

__global__ void fill_kernel(const int* __restrict__ ei, long long E,
                            int* __restrict__ cursor, int* __restrict__ esrc) {
    long long e = (long long)blockIdx.x * blockDim.x + threadIdx.x;
    if (e >= E) return;
    int s = ei[e];
    int d = ei[E + e];
    int p = atomicAdd(&cursor[d], 1);
    esrc[p] = s;
}

// ---------------- bf16-split tensor-core GEMM, cp.async 2-stage pipeline -----
// C[M,N] = A[M,K] @ B[K,N]; A pre-split AH/AL [M][Apitch kpairs], B pre-split
// BH/BL [kpair][N]. D = Ah*Bh + Ah*Bl + Al*Bh. 128x128 CTA tile, 16 kpairs/tile.
#define ASZ (128 * 20)
#define BSZ (16 * 136)
#define GEMM_SMEM_BYTES ((4 * ASZ + 4 * BSZ) * 4)

__global__ __launch_bounds__(256)
void mma_gemm_kernel(const uint32_t* __restrict__ AH, const uint32_t* __restrict__ AL,
                     int KP, int Apitch,
                     const uint32_t* __restrict__ BH, const uint32_t* __restrict__ BL,
                     float* __restrict__ C, int M, int N,
                     const float* __restrict__ bias, int bias_col0, int act,
                     uint32_t* __restrict__ outH, uint32_t* __restrict__ outL, int opitch) {
    extern __shared__ uint32_t smem[];
    uint32_t* sAH = smem;               // [2][ASZ]
    uint32_t* sAL = smem + 2 * ASZ;
    uint32_t* sBH = smem + 4 * ASZ;     // [2][BSZ]
    uint32_t* sBL = smem + 4 * ASZ + 2 * BSZ;

    const int tid  = threadIdx.x;
    const int lane = tid & 31;
    const int warp = tid >> 5;
    const int warpM = warp >> 2;   // 0..1
    const int warpN = warp & 3;    // 0..3
    const int row0 = blockIdx.y * 128;
    const int col0 = blockIdx.x * 128;

    const uint32_t smem_base = (uint32_t)__cvta_generic_to_shared(smem);
    const uint32_t aH0 = smem_base;
    const uint32_t aL0 = smem_base + 2 * ASZ * 4;
    const uint32_t bH0 = smem_base + 4 * ASZ * 4;
    const uint32_t bL0 = smem_base + (4 * ASZ + 2 * BSZ) * 4;

    // precomputed load coordinates
    const int ar   = tid >> 2;            // A row (+0 / +64)
    const int akp4 = (tid & 3) * 4;       // A kpair quad
    const int bkp  = tid >> 5;            // B kpair (+0 / +8)
    const int bc4  = (tid & 31) * 4;      // B col quad

    float acc[4][4][4];
#pragma unroll
    for (int mi = 0; mi < 4; mi++)
#pragma unroll
        for (int ni = 0; ni < 4; ni++)
#pragma unroll
            for (int q = 0; q < 4; q++) acc[mi][ni][q] = 0.0f;

    const int ntiles = (KP + 15) >> 4;

#define LOAD_STAGE(T, ST)                                                       \
    do {                                                                        \
        int ktp = (T) * 16;                                                     \
        _Pragma("unroll")                                                       \
        for (int i = 0; i < 2; i++) {                                           \
            int r  = ar + i * 64;                                               \
            int gr = row0 + r;                                                  \
            bool p = (gr < M);                                                  \
            long long off = (long long)(p ? gr : 0) * Apitch + ktp + akp4;      \
            cp16(aH0 + ((ST) * ASZ + r * 20 + akp4) * 4, &AH[off], p);          \
            cp16(aL0 + ((ST) * ASZ + r * 20 + akp4) * 4, &AL[off], p);          \
        }                                                                       \
        _Pragma("unroll")                                                       \
        for (int i = 0; i < 2; i++) {                                           \
            int kp = bkp + i * 8;                                               \
            long long off = (long long)(ktp + kp) * N + col0 + bc4;             \
            cp16(bH0 + ((ST) * BSZ + kp * 136 + bc4) * 4, &BH[off], true);      \
            cp16(bL0 + ((ST) * BSZ + kp * 136 + bc4) * 4, &BL[off], true);      \
        }                                                                       \
        cp_commit();                                                            \
    } while (0)

    LOAD_STAGE(0, 0);

    for (int t = 0; t < ntiles; t++) {
        cp_wait0();
        __syncthreads();
        if (t + 1 < ntiles) LOAD_STAGE(t + 1, (t + 1) & 1);

        const uint32_t* cAH = sAH + (t & 1) * ASZ;
        const uint32_t* cAL = sAL + (t & 1) * ASZ;
        const uint32_t* cBH = sBH + (t & 1) * BSZ;
        const uint32_t* cBL = sBL + (t & 1) * BSZ;

#pragma unroll
        for (int ks = 0; ks < 2; ks++) {
            const int kp0 = ks * 8;
            uint32_t afh[4][4], afl[4][4];
#pragma unroll
            for (int mi = 0; mi < 4; mi++) {
                int rb = warpM * 64 + mi * 16 + (lane >> 2);
                int kc = kp0 + (lane & 3);
                afh[mi][0] = cAH[rb * 20 + kc];
                afh[mi][1] = cAH[(rb + 8) * 20 + kc];
                afh[mi][2] = cAH[rb * 20 + kc + 4];
                afh[mi][3] = cAH[(rb + 8) * 20 + kc + 4];
                afl[mi][0] = cAL[rb * 20 + kc];
                afl[mi][1] = cAL[(rb + 8) * 20 + kc];
                afl[mi][2] = cAL[rb * 20 + kc + 4];
                afl[mi][3] = cAL[(rb + 8) * 20 + kc + 4];
            }
            uint32_t bfh[4][2], bfl[4][2];
#pragma unroll
            for (int ni = 0; ni < 4; ni++) {
                int cb = warpN * 32 + ni * 8 + (lane >> 2);
                bfh[ni][0] = cBH[(kp0 + (lane & 3)) * 136 + cb];
                bfh[ni][1] = cBH[(kp0 + 4 + (lane & 3)) * 136 + cb];
                bfl[ni][0] = cBL[(kp0 + (lane & 3)) * 136 + cb];
                bfl[ni][1] = cBL[(kp0 + 4 + (lane & 3)) * 136 + cb];
            }
#pragma unroll
            for (int mi = 0; mi < 4; mi++)
#pragma unroll
                for (int ni = 0; ni < 4; ni++) {
                    mma_bf16(acc[mi][ni], afh[mi], bfl[ni]);
                    mma_bf16(acc[mi][ni], afl[mi], bfh[ni]);
                    mma_bf16(acc[mi][ni], afh[mi], bfh[ni]);
                }
        }
        __syncthreads();
    }

    // ---- epilogue ----
#pragma unroll
    for (int mi = 0; mi < 4; mi++) {
#pragma unroll
        for (int ni = 0; ni < 4; ni++) {
            int c = col0 + warpN * 32 + ni * 8 + (lane & 3) * 2;
#pragma unroll
            for (int half = 0; half < 2; half++) {
                int r = row0 + warpM * 64 + mi * 16 + (lane >> 2) + half * 8;
                if (r >= M) continue;
                float v0 = acc[mi][ni][half * 2 + 0];
                float v1 = acc[mi][ni][half * 2 + 1];
                if (bias != nullptr && c >= bias_col0) {
                    v0 += bias[c - bias_col0];
                    v1 += bias[c + 1 - bias_col0];
                }
                if (act == 1) { v0 = tanhf(v0); v1 = tanhf(v1); }
                *(float2*)(C + (long long)r * N + c) = make_float2(v0, v1);
                if (outH != nullptr) {
                    uint32_t hh, ll;
                    split2(v0, v1, hh, ll);
                    outH[(long long)r * opitch + (c >> 1)] = hh;
                    outL[(long long)r * opitch + (c >> 1)] = ll;
                }
            }
        }
    }
}

// ---------------- CSR gather-reduce: agg[n] = sum_{e: dst=n} m[src_e] --------
__global__ void gather_kernel(const int* __restrict__ rowptr,
                              const int* __restrict__ esrc,
                              const float* __restrict__ out1,
                              uint32_t* __restrict__ aggH, uint32_t* __restrict__ aggL,
                              int Nn) {
    int w = (int)(((long long)blockIdx.x * blockDim.x + threadIdx.x) >> 5);
    int lane = threadIdx.x & 31;
    if (w >= Nn) return;
    int i = rowptr[w];
    const int end = rowptr[w + 1];
    float4 acc = make_float4(0.f, 0.f, 0.f, 0.f);
    int s0 = (i < end) ? esrc[i] : 0;
    int s1 = (i + 1 < end) ? esrc[i + 1] : 0;
    while (i < end) {
        int s = s0;
        s0 = s1;
        s1 = (i + 2 < end) ? esrc[i + 2] : 0;
        float4 v = *(const float4*)&out1[(long long)s * 512 + lane * 4];
        acc.x += v.x; acc.y += v.y; acc.z += v.z; acc.w += v.w;
        i++;
    }
    uint32_t h0, l0, h1, l1;
    split2(acc.x, acc.y, h0, l0);
    split2(acc.z, acc.w, h1, l1);
    long long b = (long long)w * 64 + lane * 2;
    aggH[b] = h0; aggH[b + 1] = h1;
    aggL[b] = l0; aggL[b + 1] = l1;
}

// ---------------- GRU gate fuse (float4) + h split ---------------------------
__global__ void gate_kernel(const float* __restrict__ gi,
                            const float* __restrict__ out1,
                            float* __restrict__ h,
                            uint32_t* __restrict__ hH, uint32_t* __restrict__ hL,
                            int Nn) {
    long long idx = (long long)blockIdx.x * blockDim.x + threadIdx.x;
    if (idx >= (long long)Nn * 32) return;
    long long n = idx >> 5;
    int j = (int)(idx & 31) * 4;
    const float* gir = gi + n * 384;
    const float* ghr = out1 + n * 512 + HID;
    float4 ir = *(const float4*)&gir[j];
    float4 iz = *(const float4*)&gir[j + 128];
    float4 in_ = *(const float4*)&gir[j + 256];
    float4 hr = *(const float4*)&ghr[j];
    float4 hz = *(const float4*)&ghr[j + 128];
    float4 hn = *(const float4*)&ghr[j + 256];
    float4 ho = *(const float4*)&h[n * HID + j];
    float4 res;
    {
        float r = sigmoidf_(ir.x + hr.x);
        float z = sigmoidf_(iz.x + hz.x);
        float cand = tanhf(in_.x + r * hn.x);
        res.x = (1.0f - z) * cand + z * ho.x;
    }
    {
        float r = sigmoidf_(ir.y + hr.y);
        float z = sigmoidf_(iz.y + hz.y);
        float cand = tanhf(in_.y + r * hn.y);
        res.y = (1.0f - z) * cand + z * ho.y;
    }
    {
        float r = sigmoidf_(ir.z + hr.z);
        float z = sigmoidf_(iz.z + hz.z);
        float cand = tanhf(in_.z + r * hn.z);
        res.z = (1.0f - z) * cand + z * ho.z;
    }
    {
        float r = sigmoidf_(ir.w + hr.w);
        float z = sigmoidf_(iz.w + hz.w);
        float cand = tanhf(in_.w + r * hn.w);
        res.w = (1.0f - z) * cand + z * ho.w;
    }
    *(float4*)&h[n * HID + j] = res;
    uint32_t h0, l0, h1, l1;
    split2(res.x, res.y, h0, l0);
    split2(res.z, res.w, h1, l1);
    long long b = n * 64 + (j >> 1);
    hH[b] = h0; hH[b + 1] = h1;
    hL[b] = l0; hL[b + 1] = l1;
}

// ---------------- sorted-batch pooling + head ---------------------------------
__global__ void find_starts_kernel(const int* __restrict__ batch, int Nn, int G,
                                   int* __restrict__ starts) {
    int g = blockIdx.x * blockDim.x + threadIdx.x;
    if (g > G) return;
    if (g == G) { starts[G] = Nn; return; }
    int lo = 0, hi = Nn;
    while (lo < hi) {
        int mid = (lo + hi) >> 1;
        if (batch[mid] < g) lo = mid + 1; else hi = mid;
    }
    starts[g] = lo;
}

__global__ void pool_final_kernel(const float* __restrict__ h,
                                  const int* __restrict__ starts,
                                  const float* __restrict__ w_pred,
                                  const float* __restrict__ b_pred,
                                  float* __restrict__ out) {
    int g = blockIdx.x;
    int t = threadIdx.x;   // 128
    int s = starts[g], e = starts[g + 1];
    float acc = 0.0f;
    for (int n = s; n < e; n++) acc += h[(long long)n * HID + t];
    float c = fmaxf((float)(e - s), 1.0f);
    float v = fmaxf(acc / c, 0.0f) * w_pred[t];
#pragma unroll
    for (int o = 16; o > 0; o >>= 1) v += __shfl_down_sync(0xffffffffu, v, o);
    __shared__ float ws[4];
    if ((t & 31) == 0) ws[t >> 5] = v;
    __syncthreads();
    if (t == 0) out[g] = ws[0] + ws[1] + ws[2] + ws[3] + b_pred[0];
}

// ---------------- host launcher -----------------------------------------------
extern "C" void kernel_launch(void* const* d_in, const int* in_sizes, int n_in,
                              void* d_out, int out_size) {
    const float* x       = (const float*)d_in[0];
    const int*   ei      = (const int*)d_in[1];
    const int*   batch   = (const int*)d_in[2];
    const float* W_embed = (const float*)d_in[3];
    const float* W_mpnn  = (const float*)d_in[4];
    const float* w_ih    = (const float*)d_in[5];
    const float* w_hh    = (const float*)d_in[6];
    const float* b_ih    = (const float*)d_in[7];
    const float* b_hh    = (const float*)d_in[8];
    const float* w_pred  = (const float*)d_in[9];
    const float* b_pred  = (const float*)d_in[10];
    float* out = (float*)d_out;

    int Nn = in_sizes[2];
    long long E = in_sizes[1] / 2;
    int steps = in_sizes[4] / (HID * HID);
    int F  = in_sizes[0] / Nn;      // 92
    int G = out_size;
    int KPx = F / 2;                 // 46
    int Apx = (KPx + 15) & ~15;      // 48

    static int smem_set = 0;
    if (!smem_set) {
        cudaFuncSetAttribute(mma_gemm_kernel,
                             cudaFuncAttributeMaxDynamicSharedMemorySize,
                             GEMM_SMEM_BYTES);
        smem_set = 1;
    }

    float *p_h, *p_out1, *p_gi;
    uint32_t *p_hH, *p_hL, *p_aggH, *p_aggL, *p_xH, *p_xL;
    uint32_t *p_WcatH, *p_WcatL, *p_WihTH, *p_WihTL, *p_WembH, *p_WembL;
    int *p_deg, *p_rowptr, *p_cursor, *p_esrc, *p_starts;
    cudaGetSymbolAddress((void**)&p_h,     g_h);
    cudaGetSymbolAddress((void**)&p_out1,  g_out1);
    cudaGetSymbolAddress((void**)&p_gi,    g_gi);
    cudaGetSymbolAddress((void**)&p_hH,    g_hH);
    cudaGetSymbolAddress((void**)&p_hL,    g_hL);
    cudaGetSymbolAddress((void**)&p_aggH,  g_aggH);
    cudaGetSymbolAddress((void**)&p_aggL,  g_aggL);
    cudaGetSymbolAddress((void**)&p_xH,    g_xH);
    cudaGetSymbolAddress((void**)&p_xL,    g_xL);
    cudaGetSymbolAddress((void**)&p_WcatH, g_WcatH);
    cudaGetSymbolAddress((void**)&p_WcatL, g_WcatL);
    cudaGetSymbolAddress((void**)&p_WihTH, g_WihTH);
    cudaGetSymbolAddress((void**)&p_WihTL, g_WihTL);
    cudaGetSymbolAddress((void**)&p_WembH, g_WembH);
    cudaGetSymbolAddress((void**)&p_WembL, g_WembL);
    cudaGetSymbolAddress((void**)&p_deg,   g_deg);
    cudaGetSymbolAddress((void**)&p_rowptr,g_rowptr);
    cudaGetSymbolAddress((void**)&p_cursor,g_cursor);
    cudaGetSymbolAddress((void**)&p_esrc,  g_esrc);
    cudaGetSymbolAddress((void**)&p_starts,g_starts);

    // ---- weight & input pre-split ----
    {
        int total = steps * 64 * 512;
        pack_wcat_kernel<<<(total + 255) / 256, 256>>>(W_mpnn, w_hh, p_WcatH, p_WcatL, steps);
        pack_wihT_kernel<<<(64 * 384 + 255) / 256, 256>>>(w_ih, p_WihTH, p_WihTL);
        pack_wemb_kernel<<<(48 * 128 + 255) / 256, 256>>>(W_embed, p_WembH, p_WembL, KPx);
        long long tx = (long long)Nn * Apx;
        split_x_kernel<<<(int)((tx + 255) / 256), 256>>>(x, p_xH, p_xL, Nn, F, KPx, Apx);
    }

    // ---- CSR build ----
    zero_i<<<(Nn + 255) / 256, 256>>>(p_deg, Nn);
    hist_kernel<<<(int)((E + 255) / 256), 256>>>(ei, E, p_deg);
    scan_kernel<<<1, 1024>>>(p_deg, p_rowptr, p_cursor, Nn);
    fill_kernel<<<(int)((E + 255) / 256), 256>>>(ei, E, p_cursor, p_esrc);
    find_starts_kernel<<<(G + 256) / 256, 256>>>(batch, Nn, G, p_starts);

    int mt = (Nn + 127) / 128;

    // ---- embed: h = tanh(x @ W_embed), also write hH/hL splits ----
    mma_gemm_kernel<<<dim3(1, mt), 256, GEMM_SMEM_BYTES>>>(
        p_xH, p_xL, KPx, Apx, p_WembH, p_WembL,
        p_h, Nn, HID, nullptr, 0, 1, p_hH, p_hL, 64);

    long long nh = (long long)Nn * HID;

    for (int s = 0; s < steps; s++) {
        mma_gemm_kernel<<<dim3(4, mt), 256, GEMM_SMEM_BYTES>>>(
            p_hH, p_hL, 64, 64,
            p_WcatH + (long long)s * 64 * 512, p_WcatL + (long long)s * 64 * 512,
            p_out1, Nn, 512, b_hh, HID, 0, nullptr, nullptr, 0);

        gather_kernel<<<(int)(((long long)Nn * 32 + 255) / 256), 256>>>(
            p_rowptr, p_esrc, p_out1, p_aggH, p_aggL, Nn);

        mma_gemm_kernel<<<dim3(3, mt), 256, GEMM_SMEM_BYTES>>>(
            p_aggH, p_aggL, 64, 64, p_WihTH, p_WihTL,
            p_gi, Nn, 384, b_ih, 0, 0, nullptr, nullptr, 0);

        gate_kernel<<<(int)((nh / 4 + 255) / 256), 256>>>(p_gi, p_out1, p_h, p_hH, p_hL, Nn);
    }

    pool_final_kernel<<<G, HID>>>(p_h, p_starts, w_pred, b_pred, out);
}

// round 7
// speedup vs baseline: 1.1218x; 1.1218x over previous
#include <cuda_runtime.h>
#include <cuda_bf16.h>
#include <math.h>
#include <stdint.h>

#define HID 128
#define MAX_N 100352
#define MAXSTEPS 8
#define NG 256
#define MAX_E 2000000

// ---------------- scratch (static device globals; no runtime allocation) ----
__device__ __align__(16) float    g_h   [MAX_N * HID];
__device__ __align__(16) float    g_out1[MAX_N * 512];
__device__ __align__(16) float    g_gi  [MAX_N * 384];
__device__ __align__(16) uint32_t g_hH  [MAX_N * 64];
__device__ __align__(16) uint32_t g_hL  [MAX_N * 64];
__device__ __align__(16) uint32_t g_aggH[MAX_N * 64];
__device__ __align__(16) uint32_t g_aggL[MAX_N * 64];
__device__ __align__(16) uint32_t g_xH  [MAX_N * 48];
__device__ __align__(16) uint32_t g_xL  [MAX_N * 48];
// transposed weights: [col][kpair]
__device__ __align__(16) uint32_t g_WcatTH[MAXSTEPS * 512 * 64];
__device__ __align__(16) uint32_t g_WcatTL[MAXSTEPS * 512 * 64];
__device__ __align__(16) uint32_t g_WihTH[384 * 64];
__device__ __align__(16) uint32_t g_WihTL[384 * 64];
__device__ __align__(16) uint32_t g_WembTH[128 * 48];
__device__ __align__(16) uint32_t g_WembTL[128 * 48];
__device__ int g_deg[MAX_N];
__device__ int g_rowptr[MAX_N + 1];
__device__ int g_cursor[MAX_N];
__device__ int g_esrc[MAX_E];
__device__ int g_starts[NG + 1];

// ---------------- helpers ----------------------------------------------------
__device__ __forceinline__ void split2(float x, float y, uint32_t& hi, uint32_t& lo) {
    __nv_bfloat16 hx = __float2bfloat16_rn(x);
    __nv_bfloat16 hy = __float2bfloat16_rn(y);
    float rx = x - __bfloat162float(hx);
    float ry = y - __bfloat162float(hy);
    __nv_bfloat162 h; h.x = hx; h.y = hy;
    __nv_bfloat162 l; l.x = __float2bfloat16_rn(rx); l.y = __float2bfloat16_rn(ry);
    hi = *(uint32_t*)&h;
    lo = *(uint32_t*)&l;
}

__device__ __forceinline__ void mma_bf16(float* c, const uint32_t* a, const uint32_t* b) {
    asm volatile(
        "mma.sync.aligned.m16n8k16.row.col.f32.bf16.bf16.f32 "
        "{%0,%1,%2,%3}, {%4,%5,%6,%7}, {%8,%9}, {%0,%1,%2,%3};\n"
        : "+f"(c[0]), "+f"(c[1]), "+f"(c[2]), "+f"(c[3])
        : "r"(a[0]), "r"(a[1]), "r"(a[2]), "r"(a[3]),
          "r"(b[0]), "r"(b[1]));
}

__device__ __forceinline__ void ldsm4(uint32_t& r0, uint32_t& r1,
                                      uint32_t& r2, uint32_t& r3, uint32_t addr) {
    asm volatile("ldmatrix.sync.aligned.m8n8.x4.shared.b16 {%0,%1,%2,%3}, [%4];"
                 : "=r"(r0), "=r"(r1), "=r"(r2), "=r"(r3) : "r"(addr));
}

__device__ __forceinline__ float sigmoidf_(float x) {
    return 1.0f / (1.0f + expf(-x));
}

// ---------------- small utility kernels --------------------------------------
__global__ void zero_i(int* p, int n) {
    int i = blockIdx.x * blockDim.x + threadIdx.x;
    if (i < n) p[i] = 0;
}

// ---------------- weight / input pre-split kernels (transposed layouts) ------
// WcatT: [steps][512 cols][64 kpairs]; col j<128 = W_mpnn[s][:, j], else w_hh row j-128
__global__ void pack_wcatT_kernel(const float* __restrict__ Wm,
                                  const float* __restrict__ whh,
                                  uint32_t* __restrict__ WH, uint32_t* __restrict__ WL,
                                  int steps) {
    int idx = blockIdx.x * blockDim.x + threadIdx.x;
    int total = steps * 512 * 64;
    if (idx >= total) return;
    int s = idx / (512 * 64);
    int rem = idx % (512 * 64);
    int j = rem / 64;
    int p = rem % 64;
    float a, b;
    if (j < HID) {
        a = Wm[s * HID * HID + (2 * p) * HID + j];
        b = Wm[s * HID * HID + (2 * p + 1) * HID + j];
    } else {
        int jj = j - HID;
        a = whh[jj * HID + 2 * p];
        b = whh[jj * HID + 2 * p + 1];
    }
    uint32_t h, l;
    split2(a, b, h, l);
    WH[idx] = h; WL[idx] = l;
}

// WihT (as B^T): [384 cols][64 kpairs] — col j of w_ih^T = row j of w_ih
__global__ void pack_wihT_kernel(const float* __restrict__ wih,
                                 uint32_t* __restrict__ WH, uint32_t* __restrict__ WL) {
    int idx = blockIdx.x * blockDim.x + threadIdx.x;
    if (idx >= 384 * 64) return;
    int j = idx / 64;
    int p = idx % 64;
    uint32_t h, l;
    split2(wih[j * HID + 2 * p], wih[j * HID + 2 * p + 1], h, l);
    WH[idx] = h; WL[idx] = l;
}

// WembT: [128 cols][48 kpairs padded]
__global__ void pack_wembT_kernel(const float* __restrict__ We,
                                  uint32_t* __restrict__ WH, uint32_t* __restrict__ WL,
                                  int KPx) {
    int idx = blockIdx.x * blockDim.x + threadIdx.x;
    if (idx >= 128 * 48) return;
    int j = idx / 48;
    int p = idx % 48;
    uint32_t h = 0, l = 0;
    if (p < KPx) split2(We[(2 * p) * HID + j], We[(2 * p + 1) * HID + j], h, l);
    WH[idx] = h; WL[idx] = l;
}

__global__ void split_x_kernel(const float* __restrict__ x,
                               uint32_t* __restrict__ xH, uint32_t* __restrict__ xL,
                               int Nn, int F, int KPx, int Apx) {
    long long idx = (long long)blockIdx.x * blockDim.x + threadIdx.x;
    if (idx >= (long long)Nn * Apx) return;
    int n = (int)(idx / Apx);
    int p = (int)(idx % Apx);
    uint32_t h = 0, l = 0;
    if (p < KPx) split2(x[(long long)n * F + 2 * p], x[(long long)n * F + 2 * p + 1], h, l);
    xH[idx] = h; xL[idx] = l;
}

// ---------------- CSR build ---------------------------------------------------
__global__ void hist_kernel(const int* __restrict__ ei, long long E, int* __restrict__ deg) {
    long long e = (long long)blockIdx.x * blockDim.x + threadIdx.x;
    if (e >= E) return;
    atomicAdd(&deg[ei[E + e]], 1);
}

__global__ void scan_kernel(const int* __restrict__ deg, int* __restrict__ rowptr,
                            int* __restrict__ cursor, int Nn) {
    __shared__ int warpsums[32];
    const int tid = threadIdx.x;
    const int lane = tid & 31;
    const int wid = tid >> 5;
    int carry = 0;
    for (int base = 0; base < Nn; base += 1024) {
        int idx = base + tid;
        int v = (idx < Nn) ? deg[idx] : 0;
        int x = v;
#pragma unroll
        for (int off = 1; off < 32; off <<= 1) {
            int y = __shfl_up_sync(0xffffffffu, x, off);
            if (lane >= off) x += y;
        }
        if (lane == 31) warpsums[wid] = x;
        __syncthreads();
        if (wid == 0) {
            int z = warpsums[lane];
#pragma unroll
            for (int off = 1; off < 32; off <<= 1) {
                int y = __shfl_up_sync(0xffffffffu, z, off);
                if (lane >= off) z += y;
            }
            warpsums[lane] = z;
        }
        __syncthreads();
        int pref = (wid > 0) ? warpsums[wid - 1] : 0;
        int excl = carry + pref + x - v;
        if (idx < Nn) { rowptr[idx] = excl; cursor[idx] = excl; }
        carry += warpsums[31];
        __syncthreads();
    }
    if (tid == 0) rowptr[Nn] = carry;
}

__global__ void fill_kernel(const int* __restrict__ ei, long long E,
                            int* __restrict__ cursor, int* __restrict__ esrc) {
    long long e = (long long)blockIdx.x * blockDim.x + threadIdx.x;
    if (e >= E) return;
    int s = ei[e];
    int d = ei[E + e];
    int p = atomicAdd(&cursor[d], 1);
    esrc[p] = s;
}

// ---------------- bf16-split tensor-core GEMM with ldmatrix ------------------
// C[M,N] = A[M,K] @ B[K,N]; A pre-split AH/AL [M][Apitch kpairs],
// B pre-split TRANSPOSED BTH/BTL [N][Bpitch kpairs].
// D = Ah*Bh + Ah*Bl + Al*Bh (fp32 accum). 128x128 CTA tile, 16 kpairs/tile,
// 256 thr = 8 warps (2x4), warp tile 64x32. Fragments via ldmatrix.x4.

__global__ __launch_bounds__(256)
void mma_gemm_kernel(const uint32_t* __restrict__ AH, const uint32_t* __restrict__ AL,
                     int KP, int Apitch,
                     const uint32_t* __restrict__ BTH, const uint32_t* __restrict__ BTL,
                     int Bpitch,
                     float* __restrict__ C, int M, int N,
                     const float* __restrict__ bias, int bias_col0, int act,
                     uint32_t* __restrict__ outH, uint32_t* __restrict__ outL, int opitch) {
    __shared__ uint32_t AsH[128 * 20];
    __shared__ uint32_t AsL[128 * 20];
    __shared__ uint32_t BsH[128 * 20];
    __shared__ uint32_t BsL[128 * 20];

    const int tid  = threadIdx.x;
    const int lane = tid & 31;
    const int warp = tid >> 5;
    const int warpM = warp >> 2;   // 0..1
    const int warpN = warp & 3;    // 0..3
    const int row0 = blockIdx.y * 128;
    const int col0 = blockIdx.x * 128;

    const uint32_t aHb = (uint32_t)__cvta_generic_to_shared(AsH);
    const uint32_t aLb = (uint32_t)__cvta_generic_to_shared(AsL);
    const uint32_t bHb = (uint32_t)__cvta_generic_to_shared(BsH);
    const uint32_t bLb = (uint32_t)__cvta_generic_to_shared(BsL);

    // tile-load coords (coalesced global reads; 2-way STS conflict acceptable)
    const int lr   = tid >> 2;            // row 0..63 (+64)
    const int lkp4 = (tid & 3) * 4;       // kpair quad

    // ldmatrix per-lane offsets (u32 units within tile, pitch 20)
    const int a_lane_off = (lane & 15) * 20 + ((lane >> 4) << 2);
    const int b_lane_off = ((lane & 7) + ((lane >> 4) << 3)) * 20 + (((lane >> 3) & 1) << 2);

    float acc[4][4][4];
#pragma unroll
    for (int mi = 0; mi < 4; mi++)
#pragma unroll
        for (int ni = 0; ni < 4; ni++)
#pragma unroll
            for (int q = 0; q < 4; q++) acc[mi][ni][q] = 0.0f;

    const int ntiles = (KP + 15) >> 4;

    for (int t = 0; t < ntiles; t++) {
        const int ktp = t * 16;
        // ---- A tile: 128 rows x 16 kpairs ----
#pragma unroll
        for (int i = 0; i < 2; i++) {
            int r  = lr + i * 64;
            int gr = row0 + r;
            uint4 vh = make_uint4(0, 0, 0, 0);
            uint4 vl = make_uint4(0, 0, 0, 0);
            if (gr < M) {
                long long off = (long long)gr * Apitch + ktp + lkp4;
                vh = *(const uint4*)&AH[off];
                vl = *(const uint4*)&AL[off];
            }
            *(uint4*)&AsH[r * 20 + lkp4] = vh;
            *(uint4*)&AsL[r * 20 + lkp4] = vl;
        }
        // ---- B tile (transposed): 128 cols x 16 kpairs ----
#pragma unroll
        for (int i = 0; i < 2; i++) {
            int r = lr + i * 64;
            long long off = (long long)(col0 + r) * Bpitch + ktp + lkp4;
            *(uint4*)&BsH[r * 20 + lkp4] = *(const uint4*)&BTH[off];
            *(uint4*)&BsL[r * 20 + lkp4] = *(const uint4*)&BTL[off];
        }
        __syncthreads();

#pragma unroll
        for (int ks = 0; ks < 2; ks++) {
            const int kp0 = ks * 8;
            // B fragments for the whole chunk (n32 = 2 ldsm.x4 per H/L)
            uint32_t bfh[4][2], bfl[4][2];
#pragma unroll
            for (int ni2 = 0; ni2 < 2; ni2++) {
                uint32_t off = (uint32_t)(((warpN * 32 + ni2 * 16) * 20 + kp0 + b_lane_off) * 4);
                ldsm4(bfh[ni2 * 2][0], bfh[ni2 * 2][1],
                      bfh[ni2 * 2 + 1][0], bfh[ni2 * 2 + 1][1], bHb + off);
                ldsm4(bfl[ni2 * 2][0], bfl[ni2 * 2][1],
                      bfl[ni2 * 2 + 1][0], bfl[ni2 * 2 + 1][1], bLb + off);
            }
#pragma unroll
            for (int mi = 0; mi < 4; mi++) {
                uint32_t off = (uint32_t)(((warpM * 64 + mi * 16) * 20 + kp0 + a_lane_off) * 4);
                uint32_t afh[4], afl[4];
                ldsm4(afh[0], afh[1], afh[2], afh[3], aHb + off);
                ldsm4(afl[0], afl[1], afl[2], afl[3], aLb + off);
#pragma unroll
                for (int ni = 0; ni < 4; ni++) {
                    mma_bf16(acc[mi][ni], afh, bfl[ni]);
                    mma_bf16(acc[mi][ni], afl, bfh[ni]);
                    mma_bf16(acc[mi][ni], afh, bfh[ni]);
                }
            }
        }
        __syncthreads();
    }

    // ---- epilogue ----
#pragma unroll
    for (int mi = 0; mi < 4; mi++) {
#pragma unroll
        for (int ni = 0; ni < 4; ni++) {
            int c = col0 + warpN * 32 + ni * 8 + (lane & 3) * 2;
#pragma unroll
            for (int half = 0; half < 2; half++) {
                int r = row0 + warpM * 64 + mi * 16 + (lane >> 2) + half * 8;
                if (r >= M) continue;
                float v0 = acc[mi][ni][half * 2 + 0];
                float v1 = acc[mi][ni][half * 2 + 1];
                if (bias != nullptr && c >= bias_col0) {
                    v0 += bias[c - bias_col0];
                    v1 += bias[c + 1 - bias_col0];
                }
                if (act == 1) { v0 = tanhf(v0); v1 = tanhf(v1); }
                *(float2*)(C + (long long)r * N + c) = make_float2(v0, v1);
                if (outH != nullptr) {
                    uint32_t hh, ll;
                    split2(v0, v1, hh, ll);
                    outH[(long long)r * opitch + (c >> 1)] = hh;
                    outL[(long long)r * opitch + (c >> 1)] = ll;
                }
            }
        }
    }
}

// ---------------- CSR gather-reduce: agg[n] = sum_{e: dst=n} m[src_e] --------
__global__ void gather_kernel(const int* __restrict__ rowptr,
                              const int* __restrict__ esrc,
                              const float* __restrict__ out1,
                              uint32_t* __restrict__ aggH, uint32_t* __restrict__ aggL,
                              int Nn) {
    int w = (int)(((long long)blockIdx.x * blockDim.x + threadIdx.x) >> 5);
    int lane = threadIdx.x & 31;
    if (w >= Nn) return;
    int i = rowptr[w];
    const int end = rowptr[w + 1];
    float4 acc = make_float4(0.f, 0.f, 0.f, 0.f);
    int s0 = (i < end) ? esrc[i] : 0;
    int s1 = (i + 1 < end) ? esrc[i + 1] : 0;
    while (i < end) {
        int s = s0;
        s0 = s1;
        s1 = (i + 2 < end) ? esrc[i + 2] : 0;
        float4 v = *(const float4*)&out1[(long long)s * 512 + lane * 4];
        acc.x += v.x; acc.y += v.y; acc.z += v.z; acc.w += v.w;
        i++;
    }
    uint32_t h0, l0, h1, l1;
    split2(acc.x, acc.y, h0, l0);
    split2(acc.z, acc.w, h1, l1);
    long long b = (long long)w * 64 + lane * 2;
    aggH[b] = h0; aggH[b + 1] = h1;
    aggL[b] = l0; aggL[b + 1] = l1;
}

// ---------------- GRU gate fuse (float4) + h split ---------------------------
__global__ void gate_kernel(const float* __restrict__ gi,
                            const float* __restrict__ out1,
                            float* __restrict__ h,
                            uint32_t* __restrict__ hH, uint32_t* __restrict__ hL,
                            int Nn) {
    long long idx = (long long)blockIdx.x * blockDim.x + threadIdx.x;
    if (idx >= (long long)Nn * 32) return;
    long long n = idx >> 5;
    int j = (int)(idx & 31) * 4;
    const float* gir = gi + n * 384;
    const float* ghr = out1 + n * 512 + HID;
    float4 ir = *(const float4*)&gir[j];
    float4 iz = *(const float4*)&gir[j + 128];
    float4 in_ = *(const float4*)&gir[j + 256];
    float4 hr = *(const float4*)&ghr[j];
    float4 hz = *(const float4*)&ghr[j + 128];
    float4 hn = *(const float4*)&ghr[j + 256];
    float4 ho = *(const float4*)&h[n * HID + j];
    float4 res;
    {
        float r = sigmoidf_(ir.x + hr.x);
        float z = sigmoidf_(iz.x + hz.x);
        float cand = tanhf(in_.x + r * hn.x);
        res.x = (1.0f - z) * cand + z * ho.x;
    }
    {
        float r = sigmoidf_(ir.y + hr.y);
        float z = sigmoidf_(iz.y + hz.y);
        float cand = tanhf(in_.y + r * hn.y);
        res.y = (1.0f - z) * cand + z * ho.y;
    }
    {
        float r = sigmoidf_(ir.z + hr.z);
        float z = sigmoidf_(iz.z + hz.z);
        float cand = tanhf(in_.z + r * hn.z);
        res.z = (1.0f - z) * cand + z * ho.z;
    }
    {
        float r = sigmoidf_(ir.w + hr.w);
        float z = sigmoidf_(iz.w + hz.w);
        float cand = tanhf(in_.w + r * hn.w);
        res.w = (1.0f - z) * cand + z * ho.w;
    }
    *(float4*)&h[n * HID + j] = res;
    uint32_t h0, l0, h1, l1;
    split2(res.x, res.y, h0, l0);
    split2(res.z, res.w, h1, l1);
    long long b = n * 64 + (j >> 1);
    hH[b] = h0; hH[b + 1] = h1;
    hL[b] = l0; hL[b + 1] = l1;
}

// ---------------- sorted-batch pooling + head ---------------------------------
__global__ void find_starts_kernel(const int* __restrict__ batch, int Nn, int G,
                                   int* __restrict__ starts) {
    int g = blockIdx.x * blockDim.x + threadIdx.x;
    if (g > G) return;
    if (g == G) { starts[G] = Nn; return; }
    int lo = 0, hi = Nn;
    while (lo < hi) {
        int mid = (lo + hi) >> 1;
        if (batch[mid] < g) lo = mid + 1; else hi = mid;
    }
    starts[g] = lo;
}

__global__ void pool_final_kernel(const float* __restrict__ h,
                                  const int* __restrict__ starts,
                                  const float* __restrict__ w_pred,
                                  const float* __restrict__ b_pred,
                                  float* __restrict__ out) {
    int g = blockIdx.x;
    int t = threadIdx.x;   // 128
    int s = starts[g], e = starts[g + 1];
    float acc = 0.0f;
    for (int n = s; n < e; n++) acc += h[(long long)n * HID + t];
    float c = fmaxf((float)(e - s), 1.0f);
    float v = fmaxf(acc / c, 0.0f) * w_pred[t];
#pragma unroll
    for (int o = 16; o > 0; o >>= 1) v += __shfl_down_sync(0xffffffffu, v, o);
    __shared__ float ws[4];
    if ((t & 31) == 0) ws[t >> 5] = v;
    __syncthreads();
    if (t == 0) out[g] = ws[0] + ws[1] + ws[2] + ws[3] + b_pred[0];
}

// ---------------- host launcher -----------------------------------------------
extern "C" void kernel_launch(void* const* d_in, const int* in_sizes, int n_in,
                              void* d_out, int out_size) {
    const float* x       = (const float*)d_in[0];
    const int*   ei      = (const int*)d_in[1];
    const int*   batch   = (const int*)d_in[2];
    const float* W_embed = (const float*)d_in[3];
    const float* W_mpnn  = (const float*)d_in[4];
    const float* w_ih    = (const float*)d_in[5];
    const float* w_hh    = (const float*)d_in[6];
    const float* b_ih    = (const float*)d_in[7];
    const float* b_hh    = (const float*)d_in[8];
    const float* w_pred  = (const float*)d_in[9];
    const float* b_pred  = (const float*)d_in[10];
    float* out = (float*)d_out;

    int Nn = in_sizes[2];
    long long E = in_sizes[1] / 2;
    int steps = in_sizes[4] / (HID * HID);
    int F  = in_sizes[0] / Nn;      // 92
    int G = out_size;
    int KPx = F / 2;                 // 46
    int Apx = (KPx + 15) & ~15;      // 48

    float *p_h, *p_out1, *p_gi;
    uint32_t *p_hH, *p_hL, *p_aggH, *p_aggL, *p_xH, *p_xL;
    uint32_t *p_WcatTH, *p_WcatTL, *p_WihTH, *p_WihTL, *p_WembTH, *p_WembTL;
    int *p_deg, *p_rowptr, *p_cursor, *p_esrc, *p_starts;
    cudaGetSymbolAddress((void**)&p_h,      g_h);
    cudaGetSymbolAddress((void**)&p_out1,   g_out1);
    cudaGetSymbolAddress((void**)&p_gi,     g_gi);
    cudaGetSymbolAddress((void**)&p_hH,     g_hH);
    cudaGetSymbolAddress((void**)&p_hL,     g_hL);
    cudaGetSymbolAddress((void**)&p_aggH,   g_aggH);
    cudaGetSymbolAddress((void**)&p_aggL,   g_aggL);
    cudaGetSymbolAddress((void**)&p_xH,     g_xH);
    cudaGetSymbolAddress((void**)&p_xL,     g_xL);
    cudaGetSymbolAddress((void**)&p_WcatTH, g_WcatTH);
    cudaGetSymbolAddress((void**)&p_WcatTL, g_WcatTL);
    cudaGetSymbolAddress((void**)&p_WihTH,  g_WihTH);
    cudaGetSymbolAddress((void**)&p_WihTL,  g_WihTL);
    cudaGetSymbolAddress((void**)&p_WembTH, g_WembTH);
    cudaGetSymbolAddress((void**)&p_WembTL, g_WembTL);
    cudaGetSymbolAddress((void**)&p_deg,    g_deg);
    cudaGetSymbolAddress((void**)&p_rowptr, g_rowptr);
    cudaGetSymbolAddress((void**)&p_cursor, g_cursor);
    cudaGetSymbolAddress((void**)&p_esrc,   g_esrc);
    cudaGetSymbolAddress((void**)&p_starts, g_starts);

    // ---- weight & input pre-split (transposed B layouts) ----
    {
        int total = steps * 512 * 64;
        pack_wcatT_kernel<<<(total + 255) / 256, 256>>>(W_mpnn, w_hh, p_WcatTH, p_WcatTL, steps);
        pack_wihT_kernel<<<(384 * 64 + 255) / 256, 256>>>(w_ih, p_WihTH, p_WihTL);
        pack_wembT_kernel<<<(128 * 48 + 255) / 256, 256>>>(W_embed, p_WembTH, p_WembTL, KPx);
        long long tx = (long long)Nn * Apx;
        split_x_kernel<<<(int)((tx + 255) / 256), 256>>>(x, p_xH, p_xL, Nn, F, KPx, Apx);
    }

    // ---- CSR build + graph starts ----
    zero_i<<<(Nn + 255) / 256, 256>>>(p_deg, Nn);
    hist_kernel<<<(int)((E + 255) / 256), 256>>>(ei, E, p_deg);
    scan_kernel<<<1, 1024>>>(p_deg, p_rowptr, p_cursor, Nn);
    fill_kernel<<<(int)((E + 255) / 256), 256>>>(ei, E, p_cursor, p_esrc);
    find_starts_kernel<<<(G + 256) / 256, 256>>>(batch, Nn, G, p_starts);

    int mt = (Nn + 127) / 128;

    // ---- embed: h = tanh(x @ W_embed), also write hH/hL splits ----
    mma_gemm_kernel<<<dim3(1, mt), 256>>>(
        p_xH, p_xL, KPx, Apx, p_WembTH, p_WembTL, 48,
        p_h, Nn, HID, nullptr, 0, 1, p_hH, p_hL, 64);

    long long nh = (long long)Nn * HID;

    for (int s = 0; s < steps; s++) {
        // [m | gh] = h @ [W_mpnn[s] | w_hh^T]  (+b_hh on gh cols)
        mma_gemm_kernel<<<dim3(4, mt), 256>>>(
            p_hH, p_hL, 64, 64,
            p_WcatTH + (long long)s * 512 * 64, p_WcatTL + (long long)s * 512 * 64, 64,
            p_out1, Nn, 512, b_hh, HID, 0, nullptr, nullptr, 0);

        gather_kernel<<<(int)(((long long)Nn * 32 + 255) / 256), 256>>>(
            p_rowptr, p_esrc, p_out1, p_aggH, p_aggL, Nn);

        // gi = agg @ w_ih^T + b_ih
        mma_gemm_kernel<<<dim3(3, mt), 256>>>(
            p_aggH, p_aggL, 64, 64, p_WihTH, p_WihTL, 64,
            p_gi, Nn, 384, b_ih, 0, 0, nullptr, nullptr, 0);

        gate_kernel<<<(int)((nh / 4 + 255) / 256), 256>>>(p_gi, p_out1, p_h, p_hH, p_hL, Nn);
    }

    pool_final_kernel<<<G, HID>>>(p_h, p_starts, w_pred, b_pred, out);
}